// round 7
// baseline (speedup 1.0000x reference)
#include <cuda_runtime.h>

#define N_SLOTS 524288
#define DIM     128
#define NF      138        // DIM_MEM + 1 + 1 + 7 + 1
#define DIN     1024
#define TILE    128
#define HALO    3
#define TPB     256
#define NWARPS  8
#define NTILES  (N_SLOTS / TILE)   // 4096
#define MB      304                // exactly 2 CTAs per SM on 152 SMs (all resident)
#define FB      80                 // factor-stage blocks (<=152 -> wave-1 resident, no deadlock)
#define KCH     16                 // k chunks of 64 rows

// scratch (allocation-free: __device__ globals)
__device__ __align__(16) float g_fpart[KCH][160];
__device__ float g_UpartT[DIM][MB];
__device__ float g_Zpart[MB];
__device__ int   g_cnt1 = 0;
__device__ int   g_cnt2 = 0;

__device__ __forceinline__ void rowstat(const float4 m, const float4 kv, float& d, float& q) {
    d = m.x*kv.x + m.y*kv.y + m.z*kv.z + m.w*kv.w;
    q = m.x*m.x + m.y*m.y + m.z*m.z + m.w*m.w;
}

__global__ void __launch_bounds__(TPB, 2) k_all(
    const float* __restrict__ x, const float* __restrict__ W,
    const float* __restrict__ bvec, const float* __restrict__ mem,
    float* __restrict__ out)
{
    __shared__ __align__(16) float sF[144];   // factors (key in [0,128))
    __shared__ float sP[12];                  // 0:ks 1:stab 2:ikn 3:sharp 4..10:shift
    __shared__ float sE[3][136];              // triple-buffered e window
    __shared__ float sRed[NWARPS * DIM];
    __shared__ float sZw[NWARPS];
    __shared__ int   sLast;

    const int tid = threadIdx.x, warp = tid >> 5, lane = tid & 31;
    const int bid = blockIdx.x;

    // ---------------- stage 1: factor partials (blocks 0..FB-1) ----------------
    if (bid < FB) {
        const int kb = bid / 5, fb = bid % 5;
        const int f = fb * 32 + lane;
        float a = 0.f;
        if (f < NF) {
            const int k0 = kb * 64 + warp * 8;
            #pragma unroll
            for (int i = 0; i < 8; i++)
                a += __ldg(&x[k0 + i]) * __ldg(&W[(size_t)(k0 + i) * NF + f]);
        }
        sRed[warp * 32 + lane] = a;
        __syncthreads();
        if (warp == 0) {
            float s = a;
            #pragma unroll
            for (int w = 1; w < NWARPS; w++) s += sRed[w * 32 + lane];
            g_fpart[kb][fb * 32 + lane] = s;   // lanes f>=NF write 0 (deterministic)
        }
        __threadfence();
        __syncthreads();
        if (tid == 0) atomicAdd(&g_cnt1, 1);
    }

    // ---------------- grid sync on factor partials ----------------
    if (tid == 0) {
        int v;
        do {
            asm volatile("ld.global.acquire.gpu.b32 %0, [%1];" : "=r"(v) : "l"(&g_cnt1));
            if (v < FB) __nanosleep(128);
        } while (v < FB);
    }
    __syncthreads();

    // ---------------- per-block prep (L2-hot partials) ----------------
    if (tid < 160) {
        float s = 0.f;
        #pragma unroll
        for (int p = 0; p < KCH; p++) s += g_fpart[p][tid];
        if (tid < 144) sF[tid] = (tid < NF) ? s + __ldg(&bvec[tid]) : 0.f;
    }
    __syncthreads();
    if (warp < 4) {
        const float v = sF[warp * 32 + lane];
        float sq = v * v;
        #pragma unroll
        for (int o = 16; o; o >>= 1) sq += __shfl_xor_sync(0xffffffffu, sq, o);
        if (lane == 0) sZw[warp] = sq;
    }
    __syncthreads();
    if (tid == 0) {
        const float tot = sZw[0] + sZw[1] + sZw[2] + sZw[3];
        const float ks = sF[DIM];
        sP[0] = ks;
        sP[1] = fabsf(ks);                     // stabilizer (constant cancels in normalization)
        sP[2] = 1.f / fmaxf(sqrtf(tot), 1e-8f);
        sP[3] = fmaxf(sF[NF - 1], 0.f) + 1.f;  // sharpening
        float mx = -1e30f;
        #pragma unroll
        for (int j = 0; j < 7; j++) mx = fmaxf(mx, sF[DIM + 2 + j]);
        float ssum = 0.f, ev[7];
        #pragma unroll
        for (int j = 0; j < 7; j++) { ev[j] = expf(sF[DIM + 2 + j] - mx); ssum += ev[j]; }
        #pragma unroll
        for (int j = 0; j < 7; j++) sP[4 + j] = ev[j] / ssum;
        // gate = softmax(single element) == 1.0 exactly -> previous_weighting unused
    }
    __syncthreads();

    // ---------------- main streaming loop ----------------
    const float4 kv = ((const float4*)sF)[lane];
    const float ks = sP[0], stab = sP[1], ikn = sP[2], sharp = sP[3];

    const int ts = (int)(((long long)bid * NTILES) / MB);
    const int te = (int)(((long long)(bid + 1) * NTILES) / MB);
    const int r0 = warp * 16;

    float4 acc = make_float4(0.f, 0.f, 0.f, 0.f);
    float zacc = 0.f;

    for (int t = ts, c = 0; t < te; ++t, ++c) {
        const int base = t * TILE;
        float* Ecur = sE[c % 3];
        float* Enxt = sE[(c + 1) % 3];

        // first chunk: compute left window e (positions 0..5 = rows base-3..base+2)
        if (c == 0 && warp < 6) {
            int g = base - HALO + warp;
            if (g < 0) g += N_SLOTS;
            const float4 mh0 = ((const float4*)(mem + (size_t)g * DIM))[lane];
            float d, q; rowstat(mh0, kv, d, q);
            #pragma unroll
            for (int o = 16; o; o >>= 1) {
                d += __shfl_xor_sync(0xffffffffu, d, o);
                q += __shfl_xor_sync(0xffffffffu, q, o);
            }
            if (lane == 0)
                Ecur[warp] = __expf(ks * (d * ikn * rsqrtf(fmaxf(q, 1e-16f))) - stab);
        }

        // owned burst: 16 rows (8 KB) in flight per warp
        const float* rowp = mem + (size_t)(base + r0) * DIM;
        float4 m[16];
        #pragma unroll
        for (int i = 0; i < 16; i++)
            m[i] = ((const float4*)(rowp + (size_t)i * DIM))[lane];

        // right halo rows base+128..+130 (L1-hot when re-loaded next chunk)
        float4 mh = make_float4(0.f, 0.f, 0.f, 0.f);
        const bool hh = (warp >= 5);
        if (hh) {
            int g = base + TILE + (warp - 5);
            if (g >= N_SLOTS) g -= N_SLOTS;
            mh = ((const float4*)(mem + (size_t)g * DIM))[lane];
        }

        // e for positions 6..130 (owned rows; 0..5 carried)
        #pragma unroll
        for (int i0 = 0; i0 < 16; i0 += 4) {
            float d[4], q[4];
            #pragma unroll
            for (int u = 0; u < 4; u++) rowstat(m[i0 + u], kv, d[u], q[u]);
            #pragma unroll
            for (int o = 16; o; o >>= 1) {
                #pragma unroll
                for (int u = 0; u < 4; u++) {
                    d[u] += __shfl_xor_sync(0xffffffffu, d[u], o);
                    q[u] += __shfl_xor_sync(0xffffffffu, q[u], o);
                }
            }
            if (lane == 0) {
                #pragma unroll
                for (int u = 0; u < 4; u++) {
                    const int p = 3 + r0 + i0 + u;
                    if (p >= 6) {
                        const float e = __expf(ks * (d[u] * ikn * rsqrtf(fmaxf(q[u], 1e-16f))) - stab);
                        Ecur[p] = e;
                        if (p >= 128) Enxt[p - 128] = e;   // carry for next chunk
                    }
                }
            }
        }
        // e for positions 131..133 (right halo)
        if (hh) {
            float d, q; rowstat(mh, kv, d, q);
            #pragma unroll
            for (int o = 16; o; o >>= 1) {
                d += __shfl_xor_sync(0xffffffffu, d, o);
                q += __shfl_xor_sync(0xffffffffu, q, o);
            }
            if (lane == 0) {
                const float e = __expf(ks * (d * ikn * rsqrtf(fmaxf(q, 1e-16f))) - stab);
                const int p = 131 + (warp - 5);
                Ecur[p] = e;
                Enxt[p - 128] = e;
            }
        }
        __syncthreads();   // single barrier per chunk (triple buffer makes it safe)

        // pw: lanes 0..15, one owned row each
        float pw = 0.f;
        if (lane < 16) {
            const int p0 = r0 + lane;
            float tc = 0.f;
            #pragma unroll
            for (int j = 0; j < 7; j++) tc += sP[4 + j] * Ecur[p0 + j];
            pw = __powf(tc, sharp);   // tc > 0 always
            zacc += pw;
        }
        // accumulate from registers
        #pragma unroll
        for (int r = 0; r < 16; r++) {
            const float pwb = __shfl_sync(0xffffffffu, pw, r);
            acc.x += pwb * m[r].x; acc.y += pwb * m[r].y;
            acc.z += pwb * m[r].z; acc.w += pwb * m[r].w;
        }
    }

    // ---------------- deterministic block reduction + transposed store ----------------
    __syncthreads();
    ((float4*)(sRed + warp * DIM))[lane] = acc;
    #pragma unroll
    for (int o = 16; o; o >>= 1) zacc += __shfl_xor_sync(0xffffffffu, zacc, o);
    if (lane == 0) sZw[warp] = zacc;
    __syncthreads();
    if (tid < DIM) {
        float u = 0.f;
        #pragma unroll
        for (int w = 0; w < NWARPS; w++) u += sRed[w * DIM + tid];
        g_UpartT[tid][bid] = u;
    }
    if (tid == 0) {
        float z = 0.f;
        #pragma unroll
        for (int w = 0; w < NWARPS; w++) z += sZw[w];
        g_Zpart[bid] = z;
    }
    __threadfence();
    __syncthreads();

    // ---------------- fused finisher: last-done block reduces in FIXED order ----------------
    if (tid == 0) sLast = (atomicAdd(&g_cnt2, 1) == MB - 1) ? 1 : 0;
    __syncthreads();
    if (sLast) {
        __threadfence();
        float z = 0.f;
        for (int i = lane; i < MB; i += 32) z += g_Zpart[i];
        #pragma unroll
        for (int o = 16; o; o >>= 1) z += __shfl_xor_sync(0xffffffffu, z, o);
        for (int d = warp; d < DIM; d += NWARPS) {
            float u = 0.f;
            for (int i = lane; i < MB; i += 32) u += g_UpartT[d][i];
            #pragma unroll
            for (int o = 16; o; o >>= 1) u += __shfl_xor_sync(0xffffffffu, u, o);
            if (lane == 0) out[d] = u / z;
        }
        if (tid == 0) { g_cnt1 = 0; g_cnt2 = 0; __threadfence(); }  // reset for next replay
    }
}

extern "C" void kernel_launch(void* const* d_in, const int* in_sizes, int n_in,
                              void* d_out, int out_size) {
    // Bind inputs by UNIQUE element count (robust to metadata ordering):
    // x=1024, prev=524288 (unused: gate==1), mem=67108864, W=141312, b=138
    const float *x = 0, *mem = 0, *W = 0, *b = 0;
    for (int i = 0; i < n_in; i++) {
        switch (in_sizes[i]) {
            case DIN:            x   = (const float*)d_in[i]; break;
            case N_SLOTS * DIM:  mem = (const float*)d_in[i]; break;
            case DIN * NF:       W   = (const float*)d_in[i]; break;
            case NF:             b   = (const float*)d_in[i]; break;
            default: break;      // previous_weighting (N_SLOTS): unused
        }
    }
    float* out = (float*)d_out;

    k_all<<<MB, TPB>>>(x, W, b, mem, out);
}

// round 10
// speedup vs baseline: 1.1542x; 1.1542x over previous
#include <cuda_runtime.h>

#define N_SLOTS 524288
#define DIM     128
#define NF      138        // DIM_MEM + 1 + 1 + 7 + 1
#define DIN     1024
#define TILE    128
#define HALO    3
#define TPB     256
#define NWARPS  8
#define NTILES  (N_SLOTS / TILE)   // 4096
#define MB      304                // exactly 2 CTAs per SM on 152 SMs (all resident)
#define FB      160                // factor-stage blocks (<=MB -> wave-1 resident, no deadlock)
#define KCH     32                 // k chunks of 32 rows

// scratch (allocation-free: __device__ globals)
__device__ __align__(16) float g_fpart[KCH][160];
__device__ float g_UpartT[DIM][MB];
__device__ float g_Zpart[MB];
__device__ int   g_cnt1 = 0;
__device__ int   g_cnt2 = 0;

#define FULLM 0xffffffffu

__device__ __forceinline__ void rowstat(const float4 m, const float4 kv, float& d, float& q) {
    d = m.x*kv.x + m.y*kv.y + m.z*kv.z + m.w*kv.w;
    q = m.x*m.x + m.y*m.y + m.z*m.z + m.w*m.w;
}

__device__ __forceinline__ float fullred(float v) {
    #pragma unroll
    for (int o = 16; o; o >>= 1) v += __shfl_xor_sync(FULLM, v, o);
    return v;
}

__global__ void __launch_bounds__(TPB, 2) k_all(
    const float* __restrict__ x, const float* __restrict__ W,
    const float* __restrict__ bvec, const float* __restrict__ mem,
    float* __restrict__ out)
{
    __shared__ __align__(16) float sF[144];   // factors (key in [0,128))
    __shared__ float sP[12];                  // 0:ks 1:stab 2:ikn 3:sharp 4..10:shift
    __shared__ float sE[3][136];              // triple-buffered e window
    __shared__ float sRed[NWARPS * DIM];
    __shared__ float sZw[NWARPS];
    __shared__ int   sLast;

    const int tid = threadIdx.x, warp = tid >> 5, lane = tid & 31;
    const int bid = blockIdx.x;

    // ---------------- stage 1: factor partials (blocks 0..FB-1) ----------------
    if (bid < FB) {
        const int kb = bid / 5, fb = bid % 5;
        const int f = fb * 32 + lane;
        float a = 0.f;
        if (f < NF) {
            const int k0 = kb * 32 + warp * 4;
            #pragma unroll
            for (int i = 0; i < 4; i++)
                a += __ldg(&x[k0 + i]) * __ldg(&W[(size_t)(k0 + i) * NF + f]);
        }
        sRed[warp * 32 + lane] = a;
        __syncthreads();
        if (warp == 0) {
            float s = a;
            #pragma unroll
            for (int w = 1; w < NWARPS; w++) s += sRed[w * 32 + lane];
            g_fpart[kb][fb * 32 + lane] = s;
        }
        __threadfence();
        __syncthreads();
        if (tid == 0) atomicAdd(&g_cnt1, 1);
    }

    // ---------------- grid sync on factor partials ----------------
    if (tid == 0) {
        int v;
        do {
            asm volatile("ld.global.acquire.gpu.b32 %0, [%1];" : "=r"(v) : "l"(&g_cnt1));
            if (v < FB) __nanosleep(128);
        } while (v < FB);
    }
    __syncthreads();

    // ---------------- per-block prep (L2-hot partials) ----------------
    if (tid < 160) {
        float s = 0.f;
        #pragma unroll 8
        for (int p = 0; p < KCH; p++) s += g_fpart[p][tid];
        if (tid < 144) sF[tid] = (tid < NF) ? s + __ldg(&bvec[tid]) : 0.f;
    }
    __syncthreads();
    if (warp < 4) {
        const float v = sF[warp * 32 + lane];
        float sq = fullred(v * v);
        if (lane == 0) sZw[warp] = sq;
    }
    __syncthreads();
    if (tid == 0) {
        const float tot = sZw[0] + sZw[1] + sZw[2] + sZw[3];
        const float ks = sF[DIM];
        sP[0] = ks;
        sP[1] = fabsf(ks);                     // stabilizer (constant cancels in normalization)
        sP[2] = 1.f / fmaxf(sqrtf(tot), 1e-8f);
        sP[3] = fmaxf(sF[NF - 1], 0.f) + 1.f;  // sharpening
        float mx = -1e30f;
        #pragma unroll
        for (int j = 0; j < 7; j++) mx = fmaxf(mx, sF[DIM + 2 + j]);
        float ssum = 0.f, ev[7];
        #pragma unroll
        for (int j = 0; j < 7; j++) { ev[j] = expf(sF[DIM + 2 + j] - mx); ssum += ev[j]; }
        #pragma unroll
        for (int j = 0; j < 7; j++) sP[4 + j] = ev[j] / ssum;
        // gate = softmax(single element) == 1.0 exactly -> previous_weighting unused
    }
    __syncthreads();

    // ---------------- main streaming loop ----------------
    const float4 kv = ((const float4*)sF)[lane];
    const float ks = sP[0], stab = sP[1], ikn = sP[2], sharp = sP[3];
    float sh[7];
    #pragma unroll
    for (int j = 0; j < 7; j++) sh[j] = sP[4 + j];

    const int ts = (int)(((long long)bid * NTILES) / MB);
    const int te = (int)(((long long)(bid + 1) * NTILES) / MB);
    const int r0 = warp * 16;
    const bool hw = (warp >= 5);
    const int hoff = warp - 5;

    // ---- preload tile ts ----
    float4 m[16];
    {
        const float* rowp = mem + (size_t)(ts * TILE + r0) * DIM;
        #pragma unroll
        for (int i = 0; i < 16; i++)
            m[i] = ((const float4*)(rowp + (size_t)i * DIM))[lane];
    }
    float4 mh = make_float4(0.f, 0.f, 0.f, 0.f);
    if (hw) {
        int g = ts * TILE + TILE + hoff;
        if (g >= N_SLOTS) g -= N_SLOTS;
        mh = ((const float4*)(mem + (size_t)g * DIM))[lane];
    }
    // ---- left window: rows ts*128-3..+2 -> sE[0][0..5] ----
    if (warp < 6) {
        int g = ts * TILE - HALO + warp;
        if (g < 0) g += N_SLOTS;
        const float4 v = ((const float4*)(mem + (size_t)g * DIM))[lane];
        float d, q; rowstat(v, kv, d, q);
        d = fullred(d); q = fullred(q);
        if (lane == 0)
            sE[0][warp] = __expf(ks * (d * ikn * rsqrtf(fmaxf(q, 1e-16f))) - stab);
    }

    float4 acc = make_float4(0.f, 0.f, 0.f, 0.f);
    float zacc = 0.f;

    for (int t = ts, c = 0; t < te; ++t, ++c) {
        float* Ecur = sE[c % 3];
        float* Enxt = sE[(c + 1) % 3];
        const bool more = (t + 1 < te);

        // ---- d/q/e for owned rows: multi-variable butterfly (16 shfl for 8 vars) ----
        #pragma unroll
        for (int i0 = 0; i0 < 16; i0 += 4) {
            float d[4], q[4];
            #pragma unroll
            for (int u = 0; u < 4; u++) rowstat(m[i0 + u], kv, d[u], q[u]);
            #pragma unroll
            for (int u = 0; u < 4; u++) {
                d[u] += __shfl_xor_sync(FULLM, d[u], 1);
                q[u] += __shfl_xor_sync(FULLM, q[u], 1);
            }
            float a0 = (lane & 1) ? q[0] : d[0];
            float a1 = (lane & 1) ? q[1] : d[1];
            float a2 = (lane & 1) ? q[2] : d[2];
            float a3 = (lane & 1) ? q[3] : d[3];
            a0 += __shfl_xor_sync(FULLM, a0, 2);
            a1 += __shfl_xor_sync(FULLM, a1, 2);
            a2 += __shfl_xor_sync(FULLM, a2, 2);
            a3 += __shfl_xor_sync(FULLM, a3, 2);
            float b0 = (lane & 2) ? a2 : a0;
            float b1 = (lane & 2) ? a3 : a1;
            b0 += __shfl_xor_sync(FULLM, b0, 4);
            b1 += __shfl_xor_sync(FULLM, b1, 4);
            float cc = (lane & 4) ? b1 : b0;
            cc += __shfl_xor_sync(FULLM, cc, 8);
            cc += __shfl_xor_sync(FULLM, cc, 16);
            // lane bits (b0,b1,b2): family b0 (0=d,1=q), row = 2*b1 + b2
            const float qq = __shfl_xor_sync(FULLM, cc, 1);  // q of same row onto d-lanes
            if (lane < 8 && !(lane & 1)) {
                const int row = ((lane & 2) ? 2 : 0) + ((lane & 4) ? 1 : 0);
                const int p = 3 + r0 + i0 + row;
                if (p >= 6) {
                    const float e = __expf(ks * (cc * ikn * rsqrtf(fmaxf(qq, 1e-16f))) - stab);
                    Ecur[p] = e;
                    if (p >= 128) Enxt[p - 128] = e;   // carry for next tile
                }
            }
        }

        // ---- right halo e (positions 131..133), then pipeline next halo load ----
        if (hw) {
            float d, q; rowstat(mh, kv, d, q);
            d = fullred(d); q = fullred(q);
            if (lane == 0) {
                const float e = __expf(ks * (d * ikn * rsqrtf(fmaxf(q, 1e-16f))) - stab);
                const int p = 131 + hoff;
                Ecur[p] = e;
                Enxt[p - 128] = e;
            }
            if (more) {
                int g = (t + 1) * TILE + TILE + hoff;
                if (g >= N_SLOTS) g -= N_SLOTS;
                mh = ((const float4*)(mem + (size_t)g * DIM))[lane];
            }
        }
        __syncthreads();   // single barrier per tile (triple buffer makes it safe)

        // ---- pw: lanes 0..15, one owned row each ----
        float pw = 0.f;
        if (lane < 16) {
            const int p0 = r0 + lane;
            float tc = 0.f;
            #pragma unroll
            for (int j = 0; j < 7; j++) tc += sh[j] * Ecur[p0 + j];
            pw = __powf(tc, sharp);   // tc > 0 always
            zacc += pw;
        }
        // ---- accumulate from registers; issue next tile's loads as rows retire ----
        const float* nrowp = mem + (size_t)((t + 1) * TILE + r0) * DIM;
        #pragma unroll
        for (int r = 0; r < 16; r++) {
            const float pwb = __shfl_sync(FULLM, pw, r);
            acc.x += pwb * m[r].x; acc.y += pwb * m[r].y;
            acc.z += pwb * m[r].z; acc.w += pwb * m[r].w;
            if (more)
                m[r] = ((const float4*)(nrowp + (size_t)r * DIM))[lane];
        }
    }

    // ---------------- deterministic block reduction + transposed store ----------------
    __syncthreads();
    ((float4*)(sRed + warp * DIM))[lane] = acc;
    zacc = fullred(zacc);
    if (lane == 0) sZw[warp] = zacc;
    __syncthreads();
    if (tid < DIM) {
        float u = 0.f;
        #pragma unroll
        for (int w = 0; w < NWARPS; w++) u += sRed[w * DIM + tid];
        g_UpartT[tid][bid] = u;
    }
    if (tid == 0) {
        float z = 0.f;
        #pragma unroll
        for (int w = 0; w < NWARPS; w++) z += sZw[w];
        g_Zpart[bid] = z;
    }
    __threadfence();
    __syncthreads();

    // ---------------- fused finisher: last-done block reduces in FIXED order ----------------
    if (tid == 0) sLast = (atomicAdd(&g_cnt2, 1) == MB - 1) ? 1 : 0;
    __syncthreads();
    if (sLast) {
        __threadfence();
        float z = 0.f;
        for (int i = lane; i < MB; i += 32) z += g_Zpart[i];
        z = fullred(z);
        for (int d = warp; d < DIM; d += NWARPS) {
            float u = 0.f;
            for (int i = lane; i < MB; i += 32) u += g_UpartT[d][i];
            u = fullred(u);
            if (lane == 0) out[d] = u / z;
        }
        if (tid == 0) { g_cnt1 = 0; g_cnt2 = 0; __threadfence(); }  // reset for next replay
    }
}

extern "C" void kernel_launch(void* const* d_in, const int* in_sizes, int n_in,
                              void* d_out, int out_size) {
    // Bind inputs by UNIQUE element count (robust to metadata ordering):
    // x=1024, prev=524288 (unused: gate==1), mem=67108864, W=141312, b=138
    const float *x = 0, *mem = 0, *W = 0, *b = 0;
    for (int i = 0; i < n_in; i++) {
        switch (in_sizes[i]) {
            case DIN:            x   = (const float*)d_in[i]; break;
            case N_SLOTS * DIM:  mem = (const float*)d_in[i]; break;
            case DIN * NF:       W   = (const float*)d_in[i]; break;
            case NF:             b   = (const float*)d_in[i]; break;
            default: break;      // previous_weighting (N_SLOTS): unused
        }
    }
    float* out = (float*)d_out;

    k_all<<<MB, TPB>>>(x, W, b, mem, out);
}